// round 11
// baseline (speedup 1.0000x reference)
#include <cuda_runtime.h>

// SSIM-with-logits fused kernel for GB300 (sm_103a), single-kernel version.
// input:  d_in[0] = logits  (16,1,1024,1024) f32
//         d_in[1] = target  (16,1,1024,1024) f32
// output: d_out[0] = scalar mean loss (f32)

#define IMG_H 1024
#define IMG_W 1024
#define NBATCH 16
#define TW 32              // tile width  (output)
#define TH 32              // tile height (output)
#define EW 42              // extended width  (TW + 10)
#define EH 42              // extended height (TH + 10)
#define SW 49              // smem stride for sa rows (48 cols used; odd -> conflict-free)
#define HT 42              // h transposed: stride per column (conflict-free pairs)
#define MS (TW * HT)       // per-map size of transposed h (1344 floats)
#define NBLK (NBATCH * (IMG_H/TH) * (IMG_W/TW))   // 16384

#define S_FLOATS (EH*SW)                   // 2058 (sa only; sb eliminated)
#define H_FLOATS (5*MS)                    // 6720
#define SMEM_FLOATS (S_FLOATS + H_FLOATS)  // 8778
#define SMEM_BYTES  (SMEM_FLOATS * 4)      // 35112  -> 6 blocks/SM

__device__ float    g_partial[NBLK];
__device__ unsigned g_count = 0;

typedef unsigned long long u64;

// ---- f32x2 packed helpers (sm_103a) ---------------------------------------
__device__ __forceinline__ u64 pack2(float lo, float hi) {
    u64 r;
    asm("mov.b64 %0, {%1, %2};" : "=l"(r) : "r"(__float_as_uint(lo)), "r"(__float_as_uint(hi)));
    return r;
}
__device__ __forceinline__ void unpack2(u64 v, float& lo, float& hi) {
    unsigned a, b;
    asm("mov.b64 {%0, %1}, %2;" : "=r"(a), "=r"(b) : "l"(v));
    lo = __uint_as_float(a); hi = __uint_as_float(b);
}
__device__ __forceinline__ u64 fma2(u64 a, u64 b, u64 c) {
    u64 d; asm("fma.rn.f32x2 %0, %1, %2, %3;" : "=l"(d) : "l"(a), "l"(b), "l"(c)); return d;
}
__device__ __forceinline__ u64 mul2(u64 a, u64 b) {
    u64 d; asm("mul.rn.f32x2 %0, %1, %2;" : "=l"(d) : "l"(a), "l"(b)); return d;
}
__device__ __forceinline__ u64 add2(u64 a, u64 b) {
    u64 d; asm("add.rn.f32x2 %0, %1, %2;" : "=l"(d) : "l"(a), "l"(b)); return d;
}
__device__ __forceinline__ u64 wpair(float w) {
    unsigned u = __float_as_uint(w);
    return (((u64)u) << 32) | (u64)u;
}

// Gaussian(sigma=1.5, ws=11) taps
#define G0 0.00102838f
#define G1 0.00759875f
#define G2 0.03600077f
#define G3 0.10936084f
#define G4 0.21300546f
#define G5 0.26601163f

// Scalar horizontal conv (FFMA-imm, rt_SMSP=1)
__device__ __forceinline__ float conv11(const float* x) {
    float a =  G0 * x[0];
    a = fmaf(G1, x[1],  a);
    a = fmaf(G2, x[2],  a);
    a = fmaf(G3, x[3],  a);
    a = fmaf(G4, x[4],  a);
    a = fmaf(G5, x[5],  a);
    a = fmaf(G4, x[6],  a);
    a = fmaf(G3, x[7],  a);
    a = fmaf(G2, x[8],  a);
    a = fmaf(G1, x[9],  a);
    a = fmaf(G0, x[10], a);
    return a;
}

// Product conv: conv over elementwise a[i]*b[i] without materializing the array.
__device__ __forceinline__ float conv11p(const float* x, const float* y) {
    float a =  G0 * (x[0] * y[0]);
    a = fmaf(G1, x[1]  * y[1],  a);
    a = fmaf(G2, x[2]  * y[2],  a);
    a = fmaf(G3, x[3]  * y[3],  a);
    a = fmaf(G4, x[4]  * y[4],  a);
    a = fmaf(G5, x[5]  * y[5],  a);
    a = fmaf(G4, x[6]  * y[6],  a);
    a = fmaf(G3, x[7]  * y[7],  a);
    a = fmaf(G2, x[8]  * y[8],  a);
    a = fmaf(G1, x[9]  * y[9],  a);
    a = fmaf(G0, x[10] * y[10], a);
    return a;
}

// Packed vertical conv for one map: produces out-row pairs (r0,r0+1) and (r0+2,r0+3).
__device__ __forceinline__ void vconv(const float* hc, u64& vA, u64& vB) {
    const u64* hp = (const u64*)hc;
    u64 A0 = hp[0], A1 = hp[1], A2 = hp[2], A3 = hp[3], A4 = hp[4], A5 = hp[5], A6 = hp[6];
    float l0,h0,l1,h1,l2,h2,l3,h3,l4,h4,l5,h5,l6,h6;
    unpack2(A0,l0,h0); unpack2(A1,l1,h1); unpack2(A2,l2,h2); unpack2(A3,l3,h3);
    unpack2(A4,l4,h4); unpack2(A5,l5,h5); unpack2(A6,l6,h6);
    u64 p1  = pack2(h0, l1);
    u64 p3  = pack2(h1, l2);
    u64 p5  = pack2(h2, l3);
    u64 p7  = pack2(h3, l4);
    u64 p9  = pack2(h4, l5);
    u64 p11 = pack2(h5, l6);
    u64 a;
    a = mul2(A0, wpair(G0));
    a = fma2(p1, wpair(G1), a);  a = fma2(A1, wpair(G2), a);
    a = fma2(p3, wpair(G3), a);  a = fma2(A2, wpair(G4), a);
    a = fma2(p5, wpair(G5), a);  a = fma2(A3, wpair(G4), a);
    a = fma2(p7, wpair(G3), a);  a = fma2(A4, wpair(G2), a);
    a = fma2(p9, wpair(G1), a);  a = fma2(A5, wpair(G0), a);
    vA = a;
    u64 b;
    b = mul2(A1, wpair(G0));
    b = fma2(p3, wpair(G1), b);  b = fma2(A2, wpair(G2), b);
    b = fma2(p5, wpair(G3), b);  b = fma2(A3, wpair(G4), b);
    b = fma2(p7, wpair(G5), b);  b = fma2(A4, wpair(G4), b);
    b = fma2(p9, wpair(G3), b);  b = fma2(A5, wpair(G2), b);
    b = fma2(p11, wpair(G1), b); b = fma2(A6, wpair(G0), b);
    vB = b;
}

__device__ __forceinline__ float fast_sigmoid(float x) {
    return __fdividef(1.0f, 1.0f + __expf(-x));
}

extern __shared__ float dyn_smem[];

__global__ __launch_bounds__(256, 6)
void ssim_tile_kernel(const float* __restrict__ logits,
                      const float* __restrict__ target,
                      float* __restrict__ out) {
    float* sa = dyn_smem;                // sa[EH][SW]   sigmoid(logits)
    float* h  = dyn_smem + S_FLOATS;     // h[5][TW cols][HT rows]  (transposed)

    const int tid   = threadIdx.x;
    const int tileC = blockIdx.x * TW;
    const int tileR = blockIdx.y * TH;
    const int bz    = blockIdx.z;

    const float* inb = logits + (size_t)bz * (IMG_H * IMG_W);
    const float* tgb = target + (size_t)bz * (IMG_H * IMG_W);

    const bool interior = (blockIdx.x > 0) & (blockIdx.x < (IMG_W/TW - 1)) &
                          (blockIdx.y > 0) & (blockIdx.y < (IMG_H/TH - 1));

    if (interior) {
        // ---- Phase 1 (fast): aligned float4 loads of logits only --------
        #pragma unroll
        for (int it = 0; it < 2; ++it) {
            int i = tid + it * 256;
            if (i < EH * 12) {
                int er = i / 12;
                int q  = i - er * 12;
                const float4* pr = (const float4*)(inb + (tileR + er - 5) * IMG_W + (tileC - 8));
                float4 xv = pr[q];
                float* par = sa + er * SW + 4 * q;
                par[0] = fast_sigmoid(xv.x);
                par[1] = fast_sigmoid(xv.y);
                par[2] = fast_sigmoid(xv.z);
                par[3] = fast_sigmoid(xv.w);
            }
        }
    } else {
        // ---- Phase 1 (generic): per-element reflect padding -------------
        for (int i = tid; i < EH * EW; i += 256) {
            int er = i / EW;
            int ec = i - er * EW;
            int gr = tileR + er - 5;
            int gc = tileC + ec - 5;
            if (gr < 0) gr = -gr;
            if (gr > IMG_H - 1) gr = 2 * (IMG_H - 1) - gr;
            if (gc < 0) gc = -gc;
            if (gc > IMG_W - 1) gc = 2 * (IMG_W - 1) - gc;
            sa[er * SW + ec + 3] = fast_sigmoid(inb[gr * IMG_W + gc]);
        }
    }
    __syncthreads();

    // ---- Phase 2: combined-map horizontal pass -> transposed h -----------
    // Task = (col-chunk of 8, row): 4*42 = 168 tasks. a-window from smem,
    // b-window straight from gmem (no sb buffer). All 5 maps from registers.
    if (tid < 4 * EH) {
        const int chunk = tid / EH;          // 0..3
        const int r     = tid - chunk * EH;  // 0..41
        const float* arow = sa + r * SW + chunk * 8 + 3;
        float* hdst = h + (chunk * 8) * HT + r;   // + m*MS + c*HT per output

        // b window: 18 floats covering global cols [tileC+chunk*8-5, +13)
        float wb[20];
        int boff;   // index of b[col = tileC+chunk*8-5] within wb
        if (interior) {
            const float4* pb = (const float4*)(tgb + (tileR + r - 5) * IMG_W
                                               + (tileC + chunk * 8 - 8));
            float4 b0 = pb[0], b1 = pb[1], b2 = pb[2], b3 = pb[3], b4 = pb[4];
            wb[0]=b0.x; wb[1]=b0.y; wb[2]=b0.z; wb[3]=b0.w;
            wb[4]=b1.x; wb[5]=b1.y; wb[6]=b1.z; wb[7]=b1.w;
            wb[8]=b2.x; wb[9]=b2.y; wb[10]=b2.z; wb[11]=b2.w;
            wb[12]=b3.x; wb[13]=b3.y; wb[14]=b3.z; wb[15]=b3.w;
            wb[16]=b4.x; wb[17]=b4.y; wb[18]=b4.z; wb[19]=b4.w;
            boff = 3;
        } else {
            int gr = tileR + r - 5;
            if (gr < 0) gr = -gr;
            if (gr > IMG_H - 1) gr = 2 * (IMG_H - 1) - gr;
            const float* brow = tgb + gr * IMG_W;
            #pragma unroll
            for (int i = 0; i < 18; ++i) {
                int gc = tileC + chunk * 8 - 5 + i;
                if (gc < 0) gc = -gc;
                if (gc > IMG_W - 1) gc = 2 * (IMG_W - 1) - gc;
                wb[i] = brow[gc];
            }
            boff = 0;
        }
        const float* bwin = &wb[0] + boff;   // bwin[0..17] valid

        // map1: E[b]
        #pragma unroll
        for (int c = 0; c < 8; ++c) hdst[1 * MS + c * HT] = conv11(bwin + c);

        // a window
        float wa[18];
        #pragma unroll
        for (int i = 0; i < 18; ++i) wa[i] = arow[i];

        // map0: E[a]
        #pragma unroll
        for (int c = 0; c < 8; ++c) hdst[0 * MS + c * HT] = conv11(&wa[c]);

        // map4: E[ab]
        #pragma unroll
        for (int c = 0; c < 8; ++c) hdst[4 * MS + c * HT] = conv11p(&wa[c], bwin + c);

        // map3: E[b^2]  (square b in place; b no longer needed raw)
        #pragma unroll
        for (int i = 0; i < 18; ++i) { float v = bwin[i]; wb[boff + i] = v * v; }
        #pragma unroll
        for (int c = 0; c < 8; ++c) hdst[3 * MS + c * HT] = conv11(bwin + c);

        // map2: E[a^2]
        #pragma unroll
        for (int i = 0; i < 18; ++i) wa[i] *= wa[i];
        #pragma unroll
        for (int c = 0; c < 8; ++c) hdst[2 * MS + c * HT] = conv11(&wa[c]);
    }
    __syncthreads();

    // ---- Phase 3: packed vertical pass + SSIM ----------------------------
    const int c  = tid & 31;
    const int r0 = (tid >> 5) * 4;
    const float* hb = h + c * HT + r0;

    const u64 C1p = wpair(1.0e-4f);
    const u64 C2p = wpair(9.0e-4f);
    const u64 TWOp = wpair(2.0f);
    const u64 N1p = wpair(-1.0f);

    u64 muA1, muB1, muA2, muB2;
    vconv(hb + 0 * MS, muA1, muB1);
    vconv(hb + 1 * MS, muA2, muB2);

    u64 m12A  = mul2(muA1, muA2);
    u64 m12B  = mul2(muB1, muB2);
    u64 den1A = fma2(muA2, muA2, fma2(muA1, muA1, C1p));   // m11+m22+C1
    u64 den1B = fma2(muB2, muB2, fma2(muB1, muB1, C1p));
    u64 msumA = fma2(C1p, N1p, den1A);                      // m11+m22
    u64 msumB = fma2(C1p, N1p, den1B);

    u64 eA2, eB2, tA, tB;
    vconv(hb + 2 * MS, eA2, eB2);   // E[a^2]
    vconv(hb + 3 * MS, tA, tB);     // E[b^2]
    u64 sEA = add2(eA2, tA);
    u64 sEB = add2(eB2, tB);

    u64 eabA, eabB;
    vconv(hb + 4 * MS, eabA, eabB); // E[ab]

    u64 den2A = add2(fma2(msumA, N1p, sEA), C2p);  // s11+s22+C2
    u64 den2B = add2(fma2(msumB, N1p, sEB), C2p);
    u64 s12A  = fma2(m12A, N1p, eabA);             // sigma12
    u64 s12B  = fma2(m12B, N1p, eabB);
    u64 numA  = mul2(fma2(TWOp, m12A, C1p), fma2(TWOp, s12A, C2p));
    u64 numB  = mul2(fma2(TWOp, m12B, C1p), fma2(TWOp, s12B, C2p));
    u64 denA  = mul2(den1A, den2A);
    u64 denB  = mul2(den1B, den2B);

    float n0, n1, n2, n3, d0, d1, d2, d3;
    unpack2(numA, n0, n1); unpack2(numB, n2, n3);
    unpack2(denA, d0, d1); unpack2(denB, d2, d3);

    float lsum = 0.0f;
    {
        float l;
        l = 0.5f - 0.5f * __fdividef(n0, d0); lsum += fminf(fmaxf(l, 0.0f), 0.5f);
        l = 0.5f - 0.5f * __fdividef(n1, d1); lsum += fminf(fmaxf(l, 0.0f), 0.5f);
        l = 0.5f - 0.5f * __fdividef(n2, d2); lsum += fminf(fmaxf(l, 0.0f), 0.5f);
        l = 0.5f - 0.5f * __fdividef(n3, d3); lsum += fminf(fmaxf(l, 0.0f), 0.5f);
    }

    // ---- Phase 4: block reduction -> g_partial -------------------------
    #pragma unroll
    for (int o = 16; o; o >>= 1)
        lsum += __shfl_xor_sync(0xffffffffu, lsum, o);
    __shared__ float wsum[8];
    __shared__ bool  is_last;
    if ((tid & 31) == 0) wsum[tid >> 5] = lsum;
    __syncthreads();
    if (tid == 0) {
        float t = 0.0f;
        #pragma unroll
        for (int i = 0; i < 8; ++i) t += wsum[i];
        int bid = (blockIdx.z * gridDim.y + blockIdx.y) * gridDim.x + blockIdx.x;
        g_partial[bid] = t;
        __threadfence();
        unsigned old = atomicInc(&g_count, NBLK - 1);
        is_last = (old == NBLK - 1);
    }
    __syncthreads();

    // ---- Phase 5: last block performs the deterministic final sum -------
    if (is_last) {
        __threadfence();
        const float4* p = (const float4*)g_partial;
        double acc = 0.0;
        #pragma unroll
        for (int i = 0; i < NBLK / 4 / 256; ++i) {     // 16 iterations
            float4 q = __ldcg(&p[tid + i * 256]);
            acc += (double)q.x + (double)q.y + (double)q.z + (double)q.w;
        }
        #pragma unroll
        for (int o = 16; o; o >>= 1)
            acc += __shfl_xor_sync(0xffffffffu, acc, o);
        __shared__ double dsum[8];
        if ((tid & 31) == 0) dsum[tid >> 5] = acc;
        __syncthreads();
        if (tid == 0) {
            double t = 0.0;
            #pragma unroll
            for (int i = 0; i < 8; ++i) t += dsum[i];
            out[0] = (float)(t * (1.0 / ((double)NBATCH * IMG_H * IMG_W)));
        }
    }
}

extern "C" void kernel_launch(void* const* d_in, const int* in_sizes, int n_in,
                              void* d_out, int out_size) {
    const float* logits = (const float*)d_in[0];
    const float* target = (const float*)d_in[1];
    float* out = (float*)d_out;

    cudaFuncSetAttribute(ssim_tile_kernel,
                         cudaFuncAttributeMaxDynamicSharedMemorySize, SMEM_BYTES);

    dim3 grid(IMG_W / TW, IMG_H / TH, NBATCH);   // 32 x 32 x 16
    ssim_tile_kernel<<<grid, 256, SMEM_BYTES>>>(logits, target, out);
}

// round 13
// speedup vs baseline: 1.4172x; 1.4172x over previous
#include <cuda_runtime.h>

// SSIM-with-logits fused kernel for GB300 (sm_103a), single-kernel version.
// input:  d_in[0] = logits  (16,1,1024,1024) f32
//         d_in[1] = target  (16,1,1024,1024) f32
// output: d_out[0] = scalar mean loss (f32)
//
// Algebraic fusion: E[a^2] and E[b^2] only appear as a sum in the SSIM
// denominator, and the Gaussian filter is linear, so we filter (a^2 + b^2)
// as ONE map. 4 maps total: E[a], E[b], E[a^2+b^2], E[ab].

#define IMG_H 1024
#define IMG_W 1024
#define NBATCH 16
#define TW 32              // tile width  (output)
#define TH 32              // tile height (output)
#define EW 42              // extended width  (TW + 10)
#define EH 42              // extended height (TH + 10)
#define SW 49              // smem stride for s rows (48 cols used; odd -> conflict-free)
#define HT 42              // h transposed: stride per column (conflict-free pairs)
#define MS (TW * HT)       // per-map size of transposed h (1344 floats)
#define NMAPS 4
#define NBLK (NBATCH * (IMG_H/TH) * (IMG_W/TW))   // 16384

#define S_FLOATS (2*EH*SW)                 // 4116
#define H_FLOATS (NMAPS*MS)                // 5376
#define SMEM_FLOATS (S_FLOATS + H_FLOATS)  // 9492
#define SMEM_BYTES  (SMEM_FLOATS * 4)      // 37968

__device__ float    g_partial[NBLK];
__device__ unsigned g_count = 0;

typedef unsigned long long u64;

// ---- f32x2 packed helpers (sm_103a) ---------------------------------------
__device__ __forceinline__ u64 pack2(float lo, float hi) {
    u64 r;
    asm("mov.b64 %0, {%1, %2};" : "=l"(r) : "r"(__float_as_uint(lo)), "r"(__float_as_uint(hi)));
    return r;
}
__device__ __forceinline__ void unpack2(u64 v, float& lo, float& hi) {
    unsigned a, b;
    asm("mov.b64 {%0, %1}, %2;" : "=r"(a), "=r"(b) : "l"(v));
    lo = __uint_as_float(a); hi = __uint_as_float(b);
}
__device__ __forceinline__ u64 fma2(u64 a, u64 b, u64 c) {
    u64 d; asm("fma.rn.f32x2 %0, %1, %2, %3;" : "=l"(d) : "l"(a), "l"(b), "l"(c)); return d;
}
__device__ __forceinline__ u64 mul2(u64 a, u64 b) {
    u64 d; asm("mul.rn.f32x2 %0, %1, %2;" : "=l"(d) : "l"(a), "l"(b)); return d;
}
__device__ __forceinline__ u64 add2(u64 a, u64 b) {
    u64 d; asm("add.rn.f32x2 %0, %1, %2;" : "=l"(d) : "l"(a), "l"(b)); return d;
}
__device__ __forceinline__ u64 wpair(float w) {
    unsigned u = __float_as_uint(w);
    return (((u64)u) << 32) | (u64)u;
}

// Gaussian(sigma=1.5, ws=11) taps
#define G0 0.00102838f
#define G1 0.00759875f
#define G2 0.03600077f
#define G3 0.10936084f
#define G4 0.21300546f
#define G5 0.26601163f

// Scalar horizontal conv (FFMA-imm, rt_SMSP=1)
__device__ __forceinline__ float conv11(const float* x) {
    float a =  G0 * x[0];
    a = fmaf(G1, x[1],  a);
    a = fmaf(G2, x[2],  a);
    a = fmaf(G3, x[3],  a);
    a = fmaf(G4, x[4],  a);
    a = fmaf(G5, x[5],  a);
    a = fmaf(G4, x[6],  a);
    a = fmaf(G3, x[7],  a);
    a = fmaf(G2, x[8],  a);
    a = fmaf(G1, x[9],  a);
    a = fmaf(G0, x[10], a);
    return a;
}

// Product conv: conv over elementwise a[i]*b[i] without materializing the array.
__device__ __forceinline__ float conv11p(const float* x, const float* y) {
    float a =  G0 * (x[0] * y[0]);
    a = fmaf(G1, x[1]  * y[1],  a);
    a = fmaf(G2, x[2]  * y[2],  a);
    a = fmaf(G3, x[3]  * y[3],  a);
    a = fmaf(G4, x[4]  * y[4],  a);
    a = fmaf(G5, x[5]  * y[5],  a);
    a = fmaf(G4, x[6]  * y[6],  a);
    a = fmaf(G3, x[7]  * y[7],  a);
    a = fmaf(G2, x[8]  * y[8],  a);
    a = fmaf(G1, x[9]  * y[9],  a);
    a = fmaf(G0, x[10] * y[10], a);
    return a;
}

// Packed vertical conv for one map: produces out-row pairs (r0,r0+1) and (r0+2,r0+3).
__device__ __forceinline__ void vconv(const float* hc, u64& vA, u64& vB) {
    const u64* hp = (const u64*)hc;
    u64 A0 = hp[0], A1 = hp[1], A2 = hp[2], A3 = hp[3], A4 = hp[4], A5 = hp[5], A6 = hp[6];
    float l0,h0,l1,h1,l2,h2,l3,h3,l4,h4,l5,h5,l6,h6;
    unpack2(A0,l0,h0); unpack2(A1,l1,h1); unpack2(A2,l2,h2); unpack2(A3,l3,h3);
    unpack2(A4,l4,h4); unpack2(A5,l5,h5); unpack2(A6,l6,h6);
    u64 p1  = pack2(h0, l1);
    u64 p3  = pack2(h1, l2);
    u64 p5  = pack2(h2, l3);
    u64 p7  = pack2(h3, l4);
    u64 p9  = pack2(h4, l5);
    u64 p11 = pack2(h5, l6);
    u64 a;
    a = mul2(A0, wpair(G0));
    a = fma2(p1, wpair(G1), a);  a = fma2(A1, wpair(G2), a);
    a = fma2(p3, wpair(G3), a);  a = fma2(A2, wpair(G4), a);
    a = fma2(p5, wpair(G5), a);  a = fma2(A3, wpair(G4), a);
    a = fma2(p7, wpair(G3), a);  a = fma2(A4, wpair(G2), a);
    a = fma2(p9, wpair(G1), a);  a = fma2(A5, wpair(G0), a);
    vA = a;
    u64 b;
    b = mul2(A1, wpair(G0));
    b = fma2(p3, wpair(G1), b);  b = fma2(A2, wpair(G2), b);
    b = fma2(p5, wpair(G3), b);  b = fma2(A3, wpair(G4), b);
    b = fma2(p7, wpair(G5), b);  b = fma2(A4, wpair(G4), b);
    b = fma2(p9, wpair(G3), b);  b = fma2(A5, wpair(G2), b);
    b = fma2(p11, wpair(G1), b); b = fma2(A6, wpair(G0), b);
    vB = b;
}

__device__ __forceinline__ float fast_sigmoid(float x) {
    return __fdividef(1.0f, 1.0f + __expf(-x));
}

extern __shared__ float dyn_smem[];

__global__ __launch_bounds__(256, 5)
void ssim_tile_kernel(const float* __restrict__ logits,
                      const float* __restrict__ target,
                      float* __restrict__ out) {
    float* sa = dyn_smem;                // sa[EH][SW]   sigmoid(logits)
    float* sb = dyn_smem + EH * SW;      // sb[EH][SW]   target
    float* h  = dyn_smem + S_FLOATS;     // h[4][TW cols][HT rows]  (transposed)

    const int tid   = threadIdx.x;
    const int tileC = blockIdx.x * TW;
    const int tileR = blockIdx.y * TH;
    const int bz    = blockIdx.z;

    const float* inb = logits + (size_t)bz * (IMG_H * IMG_W);
    const float* tgb = target + (size_t)bz * (IMG_H * IMG_W);

    const bool interior = (blockIdx.x > 0) & (blockIdx.x < (IMG_W/TW - 1)) &
                          (blockIdx.y > 0) & (blockIdx.y < (IMG_H/TH - 1));

    if (interior) {
        // ---- Phase 1 (fast): aligned float4 loads, no reflection --------
        #pragma unroll
        for (int it = 0; it < 2; ++it) {
            int i = tid + it * 256;
            if (i < EH * 12) {
                int er = i / 12;
                int q  = i - er * 12;
                const float4* pr = (const float4*)(inb + (tileR + er - 5) * IMG_W + (tileC - 8));
                const float4* pt = (const float4*)(tgb + (tileR + er - 5) * IMG_W + (tileC - 8));
                float4 xv = pr[q];
                float4 tv = pt[q];
                float* par = sa + er * SW + 4 * q;
                float* pbr = sb + er * SW + 4 * q;
                par[0] = fast_sigmoid(xv.x);
                par[1] = fast_sigmoid(xv.y);
                par[2] = fast_sigmoid(xv.z);
                par[3] = fast_sigmoid(xv.w);
                pbr[0] = tv.x; pbr[1] = tv.y; pbr[2] = tv.z; pbr[3] = tv.w;
            }
        }
    } else {
        // ---- Phase 1 (generic): per-element reflect padding -------------
        for (int i = tid; i < EH * EW; i += 256) {
            int er = i / EW;
            int ec = i - er * EW;
            int gr = tileR + er - 5;
            int gc = tileC + ec - 5;
            if (gr < 0) gr = -gr;
            if (gr > IMG_H - 1) gr = 2 * (IMG_H - 1) - gr;
            if (gc < 0) gc = -gc;
            if (gc > IMG_W - 1) gc = 2 * (IMG_W - 1) - gc;
            float xi = inb[gr * IMG_W + gc];
            float bt = tgb[gr * IMG_W + gc];
            sa[er * SW + ec + 3] = fast_sigmoid(xi);
            sb[er * SW + ec + 3] = bt;
        }
    }
    __syncthreads();

    // ---- Phase 2: combined-map horizontal pass -> transposed h -----------
    // Task = (col-chunk of 8, row): 4*42 = 168 tasks. Each thread loads its
    // a/b windows ONCE and computes all 4 horizontal maps from registers.
    // map0 = E[a], map1 = E[b], map2 = E[a^2 + b^2], map3 = E[ab].
    if (tid < 4 * EH) {
        const int chunk = tid / EH;          // 0..3
        const int r     = tid - chunk * EH;  // 0..41
        const float* arow = sa + r * SW + chunk * 8 + 3;
        const float* brow = sb + r * SW + chunk * 8 + 3;
        float* hdst = h + (chunk * 8) * HT + r;   // + m*MS + c*HT per output

        float wa[18], wb[18];
        #pragma unroll
        for (int i = 0; i < 18; ++i) wa[i] = arow[i];
        #pragma unroll
        for (int c = 0; c < 8; ++c) hdst[0 * MS + c * HT] = conv11(&wa[c]);

        #pragma unroll
        for (int i = 0; i < 18; ++i) wb[i] = brow[i];
        #pragma unroll
        for (int c = 0; c < 8; ++c) hdst[1 * MS + c * HT] = conv11(&wb[c]);

        // map3: E[ab]
        #pragma unroll
        for (int c = 0; c < 8; ++c) hdst[3 * MS + c * HT] = conv11p(&wa[c], &wb[c]);

        // map2: E[a^2 + b^2]  (single conv thanks to filter linearity)
        #pragma unroll
        for (int i = 0; i < 18; ++i) wa[i] = fmaf(wa[i], wa[i], wb[i] * wb[i]);
        #pragma unroll
        for (int c = 0; c < 8; ++c) hdst[2 * MS + c * HT] = conv11(&wa[c]);
    }
    __syncthreads();

    // ---- Phase 3: packed vertical pass + SSIM ----------------------------
    const int c  = tid & 31;
    const int r0 = (tid >> 5) * 4;
    const float* hb = h + c * HT + r0;

    const u64 C1p = wpair(1.0e-4f);
    const u64 C2p = wpair(9.0e-4f);
    const u64 TWOp = wpair(2.0f);
    const u64 N1p = wpair(-1.0f);

    u64 muA1, muB1, muA2, muB2;
    vconv(hb + 0 * MS, muA1, muB1);
    vconv(hb + 1 * MS, muA2, muB2);

    u64 m12A  = mul2(muA1, muA2);
    u64 m12B  = mul2(muB1, muB2);
    u64 den1A = fma2(muA2, muA2, fma2(muA1, muA1, C1p));   // m11+m22+C1
    u64 den1B = fma2(muB2, muB2, fma2(muB1, muB1, C1p));
    u64 msumA = fma2(C1p, N1p, den1A);                      // m11+m22
    u64 msumB = fma2(C1p, N1p, den1B);

    u64 sEA, sEB;
    vconv(hb + 2 * MS, sEA, sEB);   // E[a^2 + b^2]

    u64 eabA, eabB;
    vconv(hb + 3 * MS, eabA, eabB); // E[ab]

    u64 den2A = add2(fma2(msumA, N1p, sEA), C2p);  // s11+s22+C2
    u64 den2B = add2(fma2(msumB, N1p, sEB), C2p);
    u64 s12A  = fma2(m12A, N1p, eabA);             // sigma12
    u64 s12B  = fma2(m12B, N1p, eabB);
    u64 numA  = mul2(fma2(TWOp, m12A, C1p), fma2(TWOp, s12A, C2p));
    u64 numB  = mul2(fma2(TWOp, m12B, C1p), fma2(TWOp, s12B, C2p));
    u64 denA  = mul2(den1A, den2A);
    u64 denB  = mul2(den1B, den2B);

    float n0, n1, n2, n3, d0, d1, d2, d3;
    unpack2(numA, n0, n1); unpack2(numB, n2, n3);
    unpack2(denA, d0, d1); unpack2(denB, d2, d3);

    float lsum = 0.0f;
    {
        float l;
        l = 0.5f - 0.5f * __fdividef(n0, d0); lsum += fminf(fmaxf(l, 0.0f), 0.5f);
        l = 0.5f - 0.5f * __fdividef(n1, d1); lsum += fminf(fmaxf(l, 0.0f), 0.5f);
        l = 0.5f - 0.5f * __fdividef(n2, d2); lsum += fminf(fmaxf(l, 0.0f), 0.5f);
        l = 0.5f - 0.5f * __fdividef(n3, d3); lsum += fminf(fmaxf(l, 0.0f), 0.5f);
    }

    // ---- Phase 4: block reduction -> g_partial -------------------------
    #pragma unroll
    for (int o = 16; o; o >>= 1)
        lsum += __shfl_xor_sync(0xffffffffu, lsum, o);
    __shared__ float wsum[8];
    __shared__ bool  is_last;
    if ((tid & 31) == 0) wsum[tid >> 5] = lsum;
    __syncthreads();
    if (tid == 0) {
        float t = 0.0f;
        #pragma unroll
        for (int i = 0; i < 8; ++i) t += wsum[i];
        int bid = (blockIdx.z * gridDim.y + blockIdx.y) * gridDim.x + blockIdx.x;
        g_partial[bid] = t;
        __threadfence();
        unsigned old = atomicInc(&g_count, NBLK - 1);
        is_last = (old == NBLK - 1);
    }
    __syncthreads();

    // ---- Phase 5: last block performs the deterministic final sum -------
    if (is_last) {
        __threadfence();
        const float4* p = (const float4*)g_partial;
        double acc = 0.0;
        #pragma unroll
        for (int i = 0; i < NBLK / 4 / 256; ++i) {     // 16 iterations
            float4 q = __ldcg(&p[tid + i * 256]);
            acc += (double)q.x + (double)q.y + (double)q.z + (double)q.w;
        }
        #pragma unroll
        for (int o = 16; o; o >>= 1)
            acc += __shfl_xor_sync(0xffffffffu, acc, o);
        __shared__ double dsum[8];
        if ((tid & 31) == 0) dsum[tid >> 5] = acc;
        __syncthreads();
        if (tid == 0) {
            double t = 0.0;
            #pragma unroll
            for (int i = 0; i < 8; ++i) t += dsum[i];
            out[0] = (float)(t * (1.0 / ((double)NBATCH * IMG_H * IMG_W)));
        }
    }
}

extern "C" void kernel_launch(void* const* d_in, const int* in_sizes, int n_in,
                              void* d_out, int out_size) {
    const float* logits = (const float*)d_in[0];
    const float* target = (const float*)d_in[1];
    float* out = (float*)d_out;

    cudaFuncSetAttribute(ssim_tile_kernel,
                         cudaFuncAttributeMaxDynamicSharedMemorySize, SMEM_BYTES);

    dim3 grid(IMG_W / TW, IMG_H / TH, NBATCH);   // 32 x 32 x 16
    ssim_tile_kernel<<<grid, 256, SMEM_BYTES>>>(logits, target, out);
}

// round 14
// speedup vs baseline: 1.4409x; 1.0167x over previous
#include <cuda_runtime.h>

// SSIM-with-logits fused kernel for GB300 (sm_103a), single-kernel version.
// input:  d_in[0] = logits  (16,1,1024,1024) f32
//         d_in[1] = target  (16,1,1024,1024) f32
// output: d_out[0] = scalar mean loss (f32)
//
// Algebraic fusion: E[a^2]+E[b^2] filtered as ONE map (filter is linear).
// 4 maps: E[a], E[b], E[a^2+b^2], E[ab].
// Phase 2 spread over 252 threads (chunk widths 6,6,5,5,5,5).

#define IMG_H 1024
#define IMG_W 1024
#define NBATCH 16
#define TW 32              // tile width  (output)
#define TH 32              // tile height (output)
#define EW 42              // extended width  (TW + 10)
#define EH 42              // extended height (TH + 10)
#define SW 49              // smem stride for s rows (48 cols used; odd -> conflict-free)
#define HT 42              // h transposed: stride per column (conflict-free pairs)
#define MS (TW * HT)       // per-map size of transposed h (1344 floats)
#define NMAPS 4
#define NBLK (NBATCH * (IMG_H/TH) * (IMG_W/TW))   // 16384

#define S_FLOATS (2*EH*SW)                 // 4116
#define H_FLOATS (NMAPS*MS)                // 5376
#define SMEM_FLOATS (S_FLOATS + H_FLOATS)  // 9492
#define SMEM_BYTES  (SMEM_FLOATS * 4)      // 37968

__device__ float    g_partial[NBLK];
__device__ unsigned g_count = 0;

typedef unsigned long long u64;

// ---- f32x2 packed helpers (sm_103a) ---------------------------------------
__device__ __forceinline__ u64 pack2(float lo, float hi) {
    u64 r;
    asm("mov.b64 %0, {%1, %2};" : "=l"(r) : "r"(__float_as_uint(lo)), "r"(__float_as_uint(hi)));
    return r;
}
__device__ __forceinline__ void unpack2(u64 v, float& lo, float& hi) {
    unsigned a, b;
    asm("mov.b64 {%0, %1}, %2;" : "=r"(a), "=r"(b) : "l"(v));
    lo = __uint_as_float(a); hi = __uint_as_float(b);
}
__device__ __forceinline__ u64 fma2(u64 a, u64 b, u64 c) {
    u64 d; asm("fma.rn.f32x2 %0, %1, %2, %3;" : "=l"(d) : "l"(a), "l"(b), "l"(c)); return d;
}
__device__ __forceinline__ u64 mul2(u64 a, u64 b) {
    u64 d; asm("mul.rn.f32x2 %0, %1, %2;" : "=l"(d) : "l"(a), "l"(b)); return d;
}
__device__ __forceinline__ u64 add2(u64 a, u64 b) {
    u64 d; asm("add.rn.f32x2 %0, %1, %2;" : "=l"(d) : "l"(a), "l"(b)); return d;
}
__device__ __forceinline__ u64 wpair(float w) {
    unsigned u = __float_as_uint(w);
    return (((u64)u) << 32) | (u64)u;
}

// Gaussian(sigma=1.5, ws=11) taps
#define G0 0.00102838f
#define G1 0.00759875f
#define G2 0.03600077f
#define G3 0.10936084f
#define G4 0.21300546f
#define G5 0.26601163f

// Scalar horizontal conv (FFMA-imm, rt_SMSP=1)
__device__ __forceinline__ float conv11(const float* x) {
    float a =  G0 * x[0];
    a = fmaf(G1, x[1],  a);
    a = fmaf(G2, x[2],  a);
    a = fmaf(G3, x[3],  a);
    a = fmaf(G4, x[4],  a);
    a = fmaf(G5, x[5],  a);
    a = fmaf(G4, x[6],  a);
    a = fmaf(G3, x[7],  a);
    a = fmaf(G2, x[8],  a);
    a = fmaf(G1, x[9],  a);
    a = fmaf(G0, x[10], a);
    return a;
}

// Product conv: conv over elementwise a[i]*b[i] without materializing the array.
__device__ __forceinline__ float conv11p(const float* x, const float* y) {
    float a =  G0 * (x[0] * y[0]);
    a = fmaf(G1, x[1]  * y[1],  a);
    a = fmaf(G2, x[2]  * y[2],  a);
    a = fmaf(G3, x[3]  * y[3],  a);
    a = fmaf(G4, x[4]  * y[4],  a);
    a = fmaf(G5, x[5]  * y[5],  a);
    a = fmaf(G4, x[6]  * y[6],  a);
    a = fmaf(G3, x[7]  * y[7],  a);
    a = fmaf(G2, x[8]  * y[8],  a);
    a = fmaf(G1, x[9]  * y[9],  a);
    a = fmaf(G0, x[10] * y[10], a);
    return a;
}

// Packed vertical conv for one map: produces out-row pairs (r0,r0+1) and (r0+2,r0+3).
__device__ __forceinline__ void vconv(const float* hc, u64& vA, u64& vB) {
    const u64* hp = (const u64*)hc;
    u64 A0 = hp[0], A1 = hp[1], A2 = hp[2], A3 = hp[3], A4 = hp[4], A5 = hp[5], A6 = hp[6];
    float l0,h0,l1,h1,l2,h2,l3,h3,l4,h4,l5,h5,l6,h6;
    unpack2(A0,l0,h0); unpack2(A1,l1,h1); unpack2(A2,l2,h2); unpack2(A3,l3,h3);
    unpack2(A4,l4,h4); unpack2(A5,l5,h5); unpack2(A6,l6,h6);
    u64 p1  = pack2(h0, l1);
    u64 p3  = pack2(h1, l2);
    u64 p5  = pack2(h2, l3);
    u64 p7  = pack2(h3, l4);
    u64 p9  = pack2(h4, l5);
    u64 p11 = pack2(h5, l6);
    u64 a;
    a = mul2(A0, wpair(G0));
    a = fma2(p1, wpair(G1), a);  a = fma2(A1, wpair(G2), a);
    a = fma2(p3, wpair(G3), a);  a = fma2(A2, wpair(G4), a);
    a = fma2(p5, wpair(G5), a);  a = fma2(A3, wpair(G4), a);
    a = fma2(p7, wpair(G3), a);  a = fma2(A4, wpair(G2), a);
    a = fma2(p9, wpair(G1), a);  a = fma2(A5, wpair(G0), a);
    vA = a;
    u64 b;
    b = mul2(A1, wpair(G0));
    b = fma2(p3, wpair(G1), b);  b = fma2(A2, wpair(G2), b);
    b = fma2(p5, wpair(G3), b);  b = fma2(A3, wpair(G4), b);
    b = fma2(p7, wpair(G5), b);  b = fma2(A4, wpair(G4), b);
    b = fma2(p9, wpair(G3), b);  b = fma2(A5, wpair(G2), b);
    b = fma2(p11, wpair(G1), b); b = fma2(A6, wpair(G0), b);
    vB = b;
}

__device__ __forceinline__ float fast_sigmoid(float x) {
    return __fdividef(1.0f, 1.0f + __expf(-x));
}

extern __shared__ float dyn_smem[];

__global__ __launch_bounds__(256, 5)
void ssim_tile_kernel(const float* __restrict__ logits,
                      const float* __restrict__ target,
                      float* __restrict__ out) {
    float* sa = dyn_smem;                // sa[EH][SW]   sigmoid(logits)
    float* sb = dyn_smem + EH * SW;      // sb[EH][SW]   target
    float* h  = dyn_smem + S_FLOATS;     // h[4][TW cols][HT rows]  (transposed)

    const int tid   = threadIdx.x;
    const int tileC = blockIdx.x * TW;
    const int tileR = blockIdx.y * TH;
    const int bz    = blockIdx.z;

    const float* inb = logits + (size_t)bz * (IMG_H * IMG_W);
    const float* tgb = target + (size_t)bz * (IMG_H * IMG_W);

    const bool interior = (blockIdx.x > 0) & (blockIdx.x < (IMG_W/TW - 1)) &
                          (blockIdx.y > 0) & (blockIdx.y < (IMG_H/TH - 1));

    if (interior) {
        // ---- Phase 1 (fast): aligned float4 loads, no reflection --------
        #pragma unroll
        for (int it = 0; it < 2; ++it) {
            int i = tid + it * 256;
            if (i < EH * 12) {
                int er = i / 12;
                int q  = i - er * 12;
                const float4* pr = (const float4*)(inb + (tileR + er - 5) * IMG_W + (tileC - 8));
                const float4* pt = (const float4*)(tgb + (tileR + er - 5) * IMG_W + (tileC - 8));
                float4 xv = pr[q];
                float4 tv = pt[q];
                float* par = sa + er * SW + 4 * q;
                float* pbr = sb + er * SW + 4 * q;
                par[0] = fast_sigmoid(xv.x);
                par[1] = fast_sigmoid(xv.y);
                par[2] = fast_sigmoid(xv.z);
                par[3] = fast_sigmoid(xv.w);
                pbr[0] = tv.x; pbr[1] = tv.y; pbr[2] = tv.z; pbr[3] = tv.w;
            }
        }
    } else {
        // ---- Phase 1 (generic): per-element reflect padding -------------
        for (int i = tid; i < EH * EW; i += 256) {
            int er = i / EW;
            int ec = i - er * EW;
            int gr = tileR + er - 5;
            int gc = tileC + ec - 5;
            if (gr < 0) gr = -gr;
            if (gr > IMG_H - 1) gr = 2 * (IMG_H - 1) - gr;
            if (gc < 0) gc = -gc;
            if (gc > IMG_W - 1) gc = 2 * (IMG_W - 1) - gc;
            float xi = inb[gr * IMG_W + gc];
            float bt = tgb[gr * IMG_W + gc];
            sa[er * SW + ec + 3] = fast_sigmoid(xi);
            sb[er * SW + ec + 3] = bt;
        }
    }
    __syncthreads();

    // ---- Phase 2: combined-map horizontal pass -> transposed h -----------
    // Task = (chunk, row), 6 chunks of widths {6,6,5,5,5,5}: 252 threads.
    // Each thread loads its a/b windows ONCE, computes all 4 maps from regs.
    // map0 = E[a], map1 = E[b], map2 = E[a^2 + b^2], map3 = E[ab].
    if (tid < 6 * EH) {
        const int chunk = tid / EH;          // 0..5
        const int r     = tid - chunk * EH;  // 0..41
        const bool six  = chunk < 2;
        const int col0  = six ? chunk * 6 : 12 + (chunk - 2) * 5;
        const float* arow = sa + r * SW + col0 + 3;
        const float* brow = sb + r * SW + col0 + 3;
        float* hdst = h + col0 * HT + r;     // + m*MS + c*HT per output

        // Window of 16 covers width 6 (needs 16) and width 5 (needs 15);
        // max read index col0+3+15 = 45 < SW, always in-bounds.
        float wa[16], wb[16];
        #pragma unroll
        for (int i = 0; i < 16; ++i) wa[i] = arow[i];
        #pragma unroll
        for (int c = 0; c < 5; ++c) hdst[0 * MS + c * HT] = conv11(&wa[c]);
        if (six)                    hdst[0 * MS + 5 * HT] = conv11(&wa[5]);

        #pragma unroll
        for (int i = 0; i < 16; ++i) wb[i] = brow[i];
        #pragma unroll
        for (int c = 0; c < 5; ++c) hdst[1 * MS + c * HT] = conv11(&wb[c]);
        if (six)                    hdst[1 * MS + 5 * HT] = conv11(&wb[5]);

        // map3: E[ab]
        #pragma unroll
        for (int c = 0; c < 5; ++c) hdst[3 * MS + c * HT] = conv11p(&wa[c], &wb[c]);
        if (six)                    hdst[3 * MS + 5 * HT] = conv11p(&wa[5], &wb[5]);

        // map2: E[a^2 + b^2]  (single conv thanks to filter linearity)
        #pragma unroll
        for (int i = 0; i < 16; ++i) wa[i] = fmaf(wa[i], wa[i], wb[i] * wb[i]);
        #pragma unroll
        for (int c = 0; c < 5; ++c) hdst[2 * MS + c * HT] = conv11(&wa[c]);
        if (six)                    hdst[2 * MS + 5 * HT] = conv11(&wa[5]);
    }
    __syncthreads();

    // ---- Phase 3: packed vertical pass + SSIM ----------------------------
    const int c  = tid & 31;
    const int r0 = (tid >> 5) * 4;
    const float* hb = h + c * HT + r0;

    const u64 C1p = wpair(1.0e-4f);
    const u64 C2p = wpair(9.0e-4f);
    const u64 TWOp = wpair(2.0f);
    const u64 N1p = wpair(-1.0f);

    u64 muA1, muB1, muA2, muB2;
    vconv(hb + 0 * MS, muA1, muB1);
    vconv(hb + 1 * MS, muA2, muB2);

    u64 m12A  = mul2(muA1, muA2);
    u64 m12B  = mul2(muB1, muB2);
    u64 den1A = fma2(muA2, muA2, fma2(muA1, muA1, C1p));   // m11+m22+C1
    u64 den1B = fma2(muB2, muB2, fma2(muB1, muB1, C1p));
    u64 msumA = fma2(C1p, N1p, den1A);                      // m11+m22
    u64 msumB = fma2(C1p, N1p, den1B);

    u64 sEA, sEB;
    vconv(hb + 2 * MS, sEA, sEB);   // E[a^2 + b^2]

    u64 eabA, eabB;
    vconv(hb + 3 * MS, eabA, eabB); // E[ab]

    u64 den2A = add2(fma2(msumA, N1p, sEA), C2p);  // s11+s22+C2
    u64 den2B = add2(fma2(msumB, N1p, sEB), C2p);
    u64 s12A  = fma2(m12A, N1p, eabA);             // sigma12
    u64 s12B  = fma2(m12B, N1p, eabB);
    u64 numA  = mul2(fma2(TWOp, m12A, C1p), fma2(TWOp, s12A, C2p));
    u64 numB  = mul2(fma2(TWOp, m12B, C1p), fma2(TWOp, s12B, C2p));
    u64 denA  = mul2(den1A, den2A);
    u64 denB  = mul2(den1B, den2B);

    float n0, n1, n2, n3, d0, d1, d2, d3;
    unpack2(numA, n0, n1); unpack2(numB, n2, n3);
    unpack2(denA, d0, d1); unpack2(denB, d2, d3);

    float lsum = 0.0f;
    {
        float l;
        l = 0.5f - 0.5f * __fdividef(n0, d0); lsum += fminf(fmaxf(l, 0.0f), 0.5f);
        l = 0.5f - 0.5f * __fdividef(n1, d1); lsum += fminf(fmaxf(l, 0.0f), 0.5f);
        l = 0.5f - 0.5f * __fdividef(n2, d2); lsum += fminf(fmaxf(l, 0.0f), 0.5f);
        l = 0.5f - 0.5f * __fdividef(n3, d3); lsum += fminf(fmaxf(l, 0.0f), 0.5f);
    }

    // ---- Phase 4: block reduction -> g_partial -------------------------
    #pragma unroll
    for (int o = 16; o; o >>= 1)
        lsum += __shfl_xor_sync(0xffffffffu, lsum, o);
    __shared__ float wsum[8];
    __shared__ bool  is_last;
    if ((tid & 31) == 0) wsum[tid >> 5] = lsum;
    __syncthreads();
    if (tid == 0) {
        float t = 0.0f;
        #pragma unroll
        for (int i = 0; i < 8; ++i) t += wsum[i];
        int bid = (blockIdx.z * gridDim.y + blockIdx.y) * gridDim.x + blockIdx.x;
        g_partial[bid] = t;
        __threadfence();
        unsigned old = atomicInc(&g_count, NBLK - 1);
        is_last = (old == NBLK - 1);
    }
    __syncthreads();

    // ---- Phase 5: last block performs the deterministic final sum -------
    if (is_last) {
        __threadfence();
        const float4* p = (const float4*)g_partial;
        double acc = 0.0;
        #pragma unroll
        for (int i = 0; i < NBLK / 4 / 256; ++i) {     // 16 iterations
            float4 q = __ldcg(&p[tid + i * 256]);
            acc += (double)q.x + (double)q.y + (double)q.z + (double)q.w;
        }
        #pragma unroll
        for (int o = 16; o; o >>= 1)
            acc += __shfl_xor_sync(0xffffffffu, acc, o);
        __shared__ double dsum[8];
        if ((tid & 31) == 0) dsum[tid >> 5] = acc;
        __syncthreads();
        if (tid == 0) {
            double t = 0.0;
            #pragma unroll
            for (int i = 0; i < 8; ++i) t += dsum[i];
            out[0] = (float)(t * (1.0 / ((double)NBATCH * IMG_H * IMG_W)));
        }
    }
}

extern "C" void kernel_launch(void* const* d_in, const int* in_sizes, int n_in,
                              void* d_out, int out_size) {
    const float* logits = (const float*)d_in[0];
    const float* target = (const float*)d_in[1];
    float* out = (float*)d_out;

    cudaFuncSetAttribute(ssim_tile_kernel,
                         cudaFuncAttributeMaxDynamicSharedMemorySize, SMEM_BYTES);

    dim3 grid(IMG_W / TW, IMG_H / TH, NBATCH);   // 32 x 32 x 16
    ssim_tile_kernel<<<grid, 256, SMEM_BYTES>>>(logits, target, out);
}

// round 17
// speedup vs baseline: 1.5595x; 1.0823x over previous
#include <cuda_runtime.h>

// SSIM-with-logits fused kernel for GB300 (sm_103a), single-kernel version.
// input:  d_in[0] = logits  (16,1,1024,1024) f32
//         d_in[1] = target  (16,1,1024,1024) f32
// output: d_out[0] = scalar mean loss (f32)
//
// Map-packed phase 2: smem stages interleaved (sigmoid(a), b) float2 pairs;
// one f32x2 conv computes E[a],E[b] together; after an in-place transform
// (a,b)->(a^2+b^2, ab), a second f32x2 conv computes E[a^2+b^2],E[ab].

#define IMG_H 1024
#define IMG_W 1024
#define NBATCH 16
#define TW 32              // tile width  (output)
#define TH 32              // tile height (output)
#define EW 42              // extended width  (TW + 10)
#define EH 42              // extended height (TH + 10)
#define SP 43              // sab stride in float2 units (conflict-free, 1 pad slot)
#define HT 42              // h transposed: stride per column
#define MS (TW * HT)       // per-map size of transposed h (1344 floats)
#define NMAPS 4
#define NBLK (NBATCH * (IMG_H/TH) * (IMG_W/TW))   // 16384

#define SAB_U64 (EH * SP)                  // 1806 u64 = 14448 B
#define SMEM_BYTES (SAB_U64 * 8 + NMAPS * MS * 4)   // 14448 + 21504 = 35952

__device__ float    g_partial[NBLK];
__device__ unsigned g_count = 0;

typedef unsigned long long u64;

// ---- f32x2 packed helpers (sm_103a) ---------------------------------------
__device__ __forceinline__ u64 pack2(float lo, float hi) {
    u64 r;
    asm("mov.b64 %0, {%1, %2};" : "=l"(r) : "r"(__float_as_uint(lo)), "r"(__float_as_uint(hi)));
    return r;
}
__device__ __forceinline__ void unpack2(u64 v, float& lo, float& hi) {
    unsigned a, b;
    asm("mov.b64 {%0, %1}, %2;" : "=r"(a), "=r"(b) : "l"(v));
    lo = __uint_as_float(a); hi = __uint_as_float(b);
}
__device__ __forceinline__ u64 fma2(u64 a, u64 b, u64 c) {
    u64 d; asm("fma.rn.f32x2 %0, %1, %2, %3;" : "=l"(d) : "l"(a), "l"(b), "l"(c)); return d;
}
__device__ __forceinline__ u64 mul2(u64 a, u64 b) {
    u64 d; asm("mul.rn.f32x2 %0, %1, %2;" : "=l"(d) : "l"(a), "l"(b)); return d;
}
__device__ __forceinline__ u64 add2(u64 a, u64 b) {
    u64 d; asm("add.rn.f32x2 %0, %1, %2;" : "=l"(d) : "l"(a), "l"(b)); return d;
}
__device__ __forceinline__ u64 wpair(float w) {
    unsigned u = __float_as_uint(w);
    return (((u64)u) << 32) | (u64)u;
}

// Gaussian(sigma=1.5, ws=11) taps
#define G0 0.00102838f
#define G1 0.00759875f
#define G2 0.03600077f
#define G3 0.10936084f
#define G4 0.21300546f
#define G5 0.26601163f

// Packed horizontal conv over pre-packed pairs: one call = two maps.
__device__ __forceinline__ u64 conv11x2(const u64* x) {
    u64 a = mul2(x[0], wpair(G0));
    a = fma2(x[1],  wpair(G1), a);
    a = fma2(x[2],  wpair(G2), a);
    a = fma2(x[3],  wpair(G3), a);
    a = fma2(x[4],  wpair(G4), a);
    a = fma2(x[5],  wpair(G5), a);
    a = fma2(x[6],  wpair(G4), a);
    a = fma2(x[7],  wpair(G3), a);
    a = fma2(x[8],  wpair(G2), a);
    a = fma2(x[9],  wpair(G1), a);
    a = fma2(x[10], wpair(G0), a);
    return a;
}

// Packed vertical conv for one map: produces out-row pairs (r0,r0+1) and (r0+2,r0+3).
__device__ __forceinline__ void vconv(const float* hc, u64& vA, u64& vB) {
    const u64* hp = (const u64*)hc;
    u64 A0 = hp[0], A1 = hp[1], A2 = hp[2], A3 = hp[3], A4 = hp[4], A5 = hp[5], A6 = hp[6];
    float l0,h0,l1,h1,l2,h2,l3,h3,l4,h4,l5,h5,l6,h6;
    unpack2(A0,l0,h0); unpack2(A1,l1,h1); unpack2(A2,l2,h2); unpack2(A3,l3,h3);
    unpack2(A4,l4,h4); unpack2(A5,l5,h5); unpack2(A6,l6,h6);
    u64 p1  = pack2(h0, l1);
    u64 p3  = pack2(h1, l2);
    u64 p5  = pack2(h2, l3);
    u64 p7  = pack2(h3, l4);
    u64 p9  = pack2(h4, l5);
    u64 p11 = pack2(h5, l6);
    u64 a;
    a = mul2(A0, wpair(G0));
    a = fma2(p1, wpair(G1), a);  a = fma2(A1, wpair(G2), a);
    a = fma2(p3, wpair(G3), a);  a = fma2(A2, wpair(G4), a);
    a = fma2(p5, wpair(G5), a);  a = fma2(A3, wpair(G4), a);
    a = fma2(p7, wpair(G3), a);  a = fma2(A4, wpair(G2), a);
    a = fma2(p9, wpair(G1), a);  a = fma2(A5, wpair(G0), a);
    vA = a;
    u64 b;
    b = mul2(A1, wpair(G0));
    b = fma2(p3, wpair(G1), b);  b = fma2(A2, wpair(G2), b);
    b = fma2(p5, wpair(G3), b);  b = fma2(A3, wpair(G4), b);
    b = fma2(p7, wpair(G5), b);  b = fma2(A4, wpair(G4), b);
    b = fma2(p9, wpair(G3), b);  b = fma2(A5, wpair(G2), b);
    b = fma2(p11, wpair(G1), b); b = fma2(A6, wpair(G0), b);
    vB = b;
}

__device__ __forceinline__ float fast_sigmoid(float x) {
    return __fdividef(1.0f, 1.0f + __expf(-x));
}

extern __shared__ __align__(16) u64 dyn_smem_u64[];

__global__ __launch_bounds__(256, 5)
void ssim_tile_kernel(const float* __restrict__ logits,
                      const float* __restrict__ target,
                      float* __restrict__ out) {
    u64*   sab = dyn_smem_u64;                     // sab[EH][SP]  packed (a,b)
    float* h   = (float*)(dyn_smem_u64 + SAB_U64); // h[4][TW cols][HT rows]

    const int tid   = threadIdx.x;
    const int tileC = blockIdx.x * TW;
    const int tileR = blockIdx.y * TH;
    const int bz    = blockIdx.z;

    const float* inb = logits + (size_t)bz * (IMG_H * IMG_W);
    const float* tgb = target + (size_t)bz * (IMG_H * IMG_W);

    const bool interior = (blockIdx.x > 0) & (blockIdx.x < (IMG_W/TW - 1)) &
                          (blockIdx.y > 0) & (blockIdx.y < (IMG_H/TH - 1));

    // ---- Phase 1: load extended tile, sigmoid, pack (a,b) -> smem --------
    if (interior) {
        #pragma unroll
        for (int it = 0; it < 7; ++it) {
            int i = tid + it * 256;
            if (i < EH * EW) {
                int er = i / EW;
                int ec = i - er * EW;
                int gr = tileR + er - 5;
                int gc = tileC + ec - 5;
                float av = inb[gr * IMG_W + gc];
                float bv = tgb[gr * IMG_W + gc];
                sab[er * SP + ec] = pack2(fast_sigmoid(av), bv);
            }
        }
    } else {
        #pragma unroll
        for (int it = 0; it < 7; ++it) {
            int i = tid + it * 256;
            if (i < EH * EW) {
                int er = i / EW;
                int ec = i - er * EW;
                int gr = tileR + er - 5;
                int gc = tileC + ec - 5;
                if (gr < 0) gr = -gr;
                if (gr > IMG_H - 1) gr = 2 * (IMG_H - 1) - gr;
                if (gc < 0) gc = -gc;
                if (gc > IMG_W - 1) gc = 2 * (IMG_W - 1) - gc;
                float av = inb[gr * IMG_W + gc];
                float bv = tgb[gr * IMG_W + gc];
                sab[er * SP + ec] = pack2(fast_sigmoid(av), bv);
            }
        }
    }
    __syncthreads();

    // ---- Phase 2: packed horizontal pass -> transposed h -----------------
    // Task = (chunk, row), 6 chunks widths {6,6,5,5,5,5}: 252 threads.
    // conv11x2 on (a,b) pairs -> maps 0,1; in-place transform to
    // (a^2+b^2, ab) pairs -> conv11x2 -> maps 2,3.
    if (tid < 6 * EH) {
        const int chunk = tid / EH;          // 0..5
        const int r     = tid - chunk * EH;  // 0..41
        const bool six  = chunk < 2;
        const int col0  = six ? chunk * 6 : 12 + (chunk - 2) * 5;
        const u64* srow = sab + r * SP + col0;
        float* hdst = h + col0 * HT + r;     // + m*MS + c*HT per output

        // Window: width-6 needs w[0..15], width-5 needs w[0..14]. Index
        // col0+15 = 42 max, which is the in-stride pad slot (defined memory).
        u64 w[16];
        #pragma unroll
        for (int i = 0; i < 16; ++i) w[i] = srow[i];

        // maps 0,1: E[a], E[b]
        #pragma unroll
        for (int c = 0; c < 5; ++c) {
            float ea, eb; unpack2(conv11x2(&w[c]), ea, eb);
            hdst[0 * MS + c * HT] = ea;
            hdst[1 * MS + c * HT] = eb;
        }
        if (six) {
            float ea, eb; unpack2(conv11x2(&w[5]), ea, eb);
            hdst[0 * MS + 5 * HT] = ea;
            hdst[1 * MS + 5 * HT] = eb;
        }

        // transform: (a, b) -> (a^2 + b^2, a*b)
        #pragma unroll
        for (int i = 0; i < 16; ++i) {
            float a, b; unpack2(w[i], a, b);
            w[i] = pack2(fmaf(a, a, b * b), a * b);
        }

        // maps 2,3: E[a^2+b^2], E[ab]
        #pragma unroll
        for (int c = 0; c < 5; ++c) {
            float es, ep; unpack2(conv11x2(&w[c]), es, ep);
            hdst[2 * MS + c * HT] = es;
            hdst[3 * MS + c * HT] = ep;
        }
        if (six) {
            float es, ep; unpack2(conv11x2(&w[5]), es, ep);
            hdst[2 * MS + 5 * HT] = es;
            hdst[3 * MS + 5 * HT] = ep;
        }
    }
    __syncthreads();

    // ---- Phase 3: packed vertical pass + SSIM ----------------------------
    const int c  = tid & 31;
    const int r0 = (tid >> 5) * 4;
    const float* hb = h + c * HT + r0;

    const u64 C1p = wpair(1.0e-4f);
    const u64 C2p = wpair(9.0e-4f);
    const u64 TWOp = wpair(2.0f);
    const u64 N1p = wpair(-1.0f);

    u64 muA1, muB1, muA2, muB2;
    vconv(hb + 0 * MS, muA1, muB1);
    vconv(hb + 1 * MS, muA2, muB2);

    u64 m12A  = mul2(muA1, muA2);
    u64 m12B  = mul2(muB1, muB2);
    u64 den1A = fma2(muA2, muA2, fma2(muA1, muA1, C1p));   // m11+m22+C1
    u64 den1B = fma2(muB2, muB2, fma2(muB1, muB1, C1p));
    u64 msumA = fma2(C1p, N1p, den1A);                      // m11+m22
    u64 msumB = fma2(C1p, N1p, den1B);

    u64 sEA, sEB;
    vconv(hb + 2 * MS, sEA, sEB);   // E[a^2 + b^2]

    u64 eabA, eabB;
    vconv(hb + 3 * MS, eabA, eabB); // E[ab]

    u64 den2A = add2(fma2(msumA, N1p, sEA), C2p);  // s11+s22+C2
    u64 den2B = add2(fma2(msumB, N1p, sEB), C2p);
    u64 s12A  = fma2(m12A, N1p, eabA);             // sigma12
    u64 s12B  = fma2(m12B, N1p, eabB);
    u64 numA  = mul2(fma2(TWOp, m12A, C1p), fma2(TWOp, s12A, C2p));
    u64 numB  = mul2(fma2(TWOp, m12B, C1p), fma2(TWOp, s12B, C2p));
    u64 denA  = mul2(den1A, den2A);
    u64 denB  = mul2(den1B, den2B);

    float n0, n1, n2, n3, d0, d1, d2, d3;
    unpack2(numA, n0, n1); unpack2(numB, n2, n3);
    unpack2(denA, d0, d1); unpack2(denB, d2, d3);

    float lsum = 0.0f;
    {
        float l;
        l = 0.5f - 0.5f * __fdividef(n0, d0); lsum += fminf(fmaxf(l, 0.0f), 0.5f);
        l = 0.5f - 0.5f * __fdividef(n1, d1); lsum += fminf(fmaxf(l, 0.0f), 0.5f);
        l = 0.5f - 0.5f * __fdividef(n2, d2); lsum += fminf(fmaxf(l, 0.0f), 0.5f);
        l = 0.5f - 0.5f * __fdividef(n3, d3); lsum += fminf(fmaxf(l, 0.0f), 0.5f);
    }

    // ---- Phase 4: block reduction -> g_partial -------------------------
    #pragma unroll
    for (int o = 16; o; o >>= 1)
        lsum += __shfl_xor_sync(0xffffffffu, lsum, o);
    __shared__ float wsum[8];
    __shared__ bool  is_last;
    if ((tid & 31) == 0) wsum[tid >> 5] = lsum;
    __syncthreads();
    if (tid == 0) {
        float t = 0.0f;
        #pragma unroll
        for (int i = 0; i < 8; ++i) t += wsum[i];
        int bid = (blockIdx.z * gridDim.y + blockIdx.y) * gridDim.x + blockIdx.x;
        g_partial[bid] = t;
        __threadfence();
        unsigned old = atomicInc(&g_count, NBLK - 1);
        is_last = (old == NBLK - 1);
    }
    __syncthreads();

    // ---- Phase 5: last block performs the deterministic final sum -------
    if (is_last) {
        __threadfence();
        const float4* p = (const float4*)g_partial;
        double acc = 0.0;
        #pragma unroll
        for (int i = 0; i < NBLK / 4 / 256; ++i) {     // 16 iterations
            float4 q = __ldcg(&p[tid + i * 256]);
            acc += (double)q.x + (double)q.y + (double)q.z + (double)q.w;
        }
        #pragma unroll
        for (int o = 16; o; o >>= 1)
            acc += __shfl_xor_sync(0xffffffffu, acc, o);
        __shared__ double dsum[8];
        if ((tid & 31) == 0) dsum[tid >> 5] = acc;
        __syncthreads();
        if (tid == 0) {
            double t = 0.0;
            #pragma unroll
            for (int i = 0; i < 8; ++i) t += dsum[i];
            out[0] = (float)(t * (1.0 / ((double)NBATCH * IMG_H * IMG_W)));
        }
    }
}

extern "C" void kernel_launch(void* const* d_in, const int* in_sizes, int n_in,
                              void* d_out, int out_size) {
    const float* logits = (const float*)d_in[0];
    const float* target = (const float*)d_in[1];
    float* out = (float*)d_out;

    cudaFuncSetAttribute(ssim_tile_kernel,
                         cudaFuncAttributeMaxDynamicSharedMemorySize, SMEM_BYTES);

    dim3 grid(IMG_W / TW, IMG_H / TH, NBATCH);   // 32 x 32 x 16
    ssim_tile_kernel<<<grid, 256, SMEM_BYTES>>>(logits, target, out);
}